// round 4
// baseline (speedup 1.0000x reference)
#include <cuda_runtime.h>
#include <cuda_bf16.h>
#include <cstdint>

// Problem constants (fixed by setup_inputs)
#define HPM       8
#define NUM_PAGES 4096
#define PAGE_SIZE 16
#define DPM       128
#define MAX_SEQS  8
#define MAX_PPS   256
#define D4        (DPM / 4)                                    // 32 float4 per row
#define PAGES_ELEMS (2LL * HPM * NUM_PAGES * PAGE_SIZE * DPM)  // 134,217,728 floats
#define INNER_F4  (HPM * NUM_PAGES * PAGE_SIZE * D4)           // 1<<24 float4 per tensor
#define TOTAL_F4  (2u * INNER_F4)                              // 1<<25
#define NTHREADS  256
#define F4_PER_BLOCK 1024u                                     // == 2 pages
#define NBLOCKS   (TOTAL_F4 / F4_PER_BLOCK)                    // 32768

// ---------------------------------------------------------------------------
// Single kernel, no cross-block dependency. Each block recomputes the
// allocation rank for the 2 pages it covers from page_indices (16KB,
// L2-resident after wave 1). Block 0 also emits the two small outputs.
// ---------------------------------------------------------------------------
__global__ void __launch_bounds__(NTHREADS)
fused_pages_kernel(const float4* __restrict__ key,          // [1, S, H, D]
                   const float4* __restrict__ value,
                   const float4* __restrict__ key_pages,    // [H, P, PS, D]
                   const float4* __restrict__ value_pages,
                   const int*    __restrict__ page_indices,
                   const int*    __restrict__ seq_page_indices,
                   const int*    __restrict__ slot_p,
                   const int*    __restrict__ true_length_p,
                   float4* __restrict__ out,                 // [2, H, P, PS, D]
                   float*  __restrict__ out_pi,              // [4096]
                   float*  __restrict__ out_spi)             // [8, 256]
{
    __shared__ int s_w[8];      // per-warp partial sums / scan bases
    __shared__ int s_f[2];      // free flags of p0, p1
    __shared__ int s_S0;        // rank of p0

    const int tid  = threadIdx.x;
    const int lane = tid & 31;
    const int wrp  = tid >> 5;

    // Pages this block covers (1024 f4 = 2 pages, h/t-aligned)
    const unsigned p0 = (2u * blockIdx.x) & (NUM_PAGES - 1);  // even
    const unsigned p1 = p0 + 1;

    // --- Load free flags: 16 pages per thread, vectorized int4 ---
    int fl[16];
    {
        const int4* pi4 = (const int4*)page_indices;
#pragma unroll
        for (int k = 0; k < 4; k++) {
            int4 v = __ldg(&pi4[tid * 4 + k]);
            int base_p = tid * 16 + k * 4;
            fl[k * 4 + 0] = (base_p + 0 >= 1) && (v.x == 0);
            fl[k * 4 + 1] = (v.y == 0);
            fl[k * 4 + 2] = (v.z == 0);
            fl[k * 4 + 3] = (v.w == 0);
        }
    }

    // --- Rank of p0: count free pages with index < p0 ---
    int part = 0;
#pragma unroll
    for (int j = 0; j < 16; j++) {
        unsigned p = tid * 16 + j;
        part += fl[j] & (p < p0);
    }
#pragma unroll
    for (int off = 16; off > 0; off >>= 1)
        part += __shfl_xor_sync(0xffffffffu, part, off);
    if (lane == 0) s_w[wrp] = part;

    // free flags of p0, p1 (owner threads)
    if (tid == (int)(p0 >> 4)) s_f[0] = fl[p0 & 15];
    if (tid == (int)(p1 >> 4)) s_f[1] = fl[p1 & 15];
    __syncthreads();

    if (tid == 0) {
        int s = 0;
#pragma unroll
        for (int i = 0; i < 8; i++) s += s_w[i];
        s_S0 = s;
    }
    __syncthreads();

    const int tl = __ldg(true_length_p);
    int nb = (tl + PAGE_SIZE - 1) / PAGE_SIZE;
    if (nb > MAX_PPS) nb = MAX_PPS;

    const int S0 = s_S0;
    const int f0 = s_f[0], f1 = s_f[1];
    const int b0 = (f0 && S0 < nb)        ? S0        : -1;
    const int b1 = (f1 && (S0 + f0) < nb) ? (S0 + f0) : -1;

    // ---------------- Block 0 only: small outputs (full scan) ----------------
    if (blockIdx.x == 0) {
        __shared__ int s_base[8];
        __shared__ int s_pob[MAX_PPS];

        int cnt = 0;
#pragma unroll
        for (int j = 0; j < 16; j++) cnt += fl[j];

        int incl = cnt;
#pragma unroll
        for (int off = 1; off < 32; off <<= 1) {
            int n = __shfl_up_sync(0xffffffffu, incl, off);
            if (lane >= off) incl += n;
        }
        if (lane == 31) s_base[wrp] = incl;
        __syncthreads();
        if (wrp == 0 && lane < 8) {
            int v = s_base[lane];
            int s = v;
#pragma unroll
            for (int off = 1; off < 8; off <<= 1) {
                int n = __shfl_up_sync(0xffu, s, off);
                if (lane >= off) s += n;
            }
            s_base[lane] = s - v;   // exclusive warp base
        }
        __syncthreads();

        int run = s_base[wrp] + (incl - cnt);
#pragma unroll
        for (int j = 0; j < 16; j++) {
            int p = tid * 16 + j;
            int b = -1;
            if (fl[j]) {
                if (run < nb) { b = run; s_pob[run] = p; }
                run++;
            }
            out_pi[p] = (b >= 0) ? 1.0f : (float)__ldg(&page_indices[p]);
        }
        __syncthreads();

        const int slot = __ldg(slot_p);
        for (int i = tid; i < MAX_SEQS * MAX_PPS; i += NTHREADS) {
            int r = i >> 8, c = i & 255;
            float v = (float)__ldg(&seq_page_indices[i]);
            if (r == slot && c < nb) v = (float)s_pob[c];
            out_spi[i] = v;
        }
    }

    // ---------------- Copy phase (unchanged from R2 winner) ----------------
    const unsigned base = blockIdx.x * F4_PER_BLOCK + tid;
    const unsigned t = base >> 24;                      // 0 = key, 1 = value (block-uniform)
    const float4* __restrict__ kv    = t ? value       : key;
    const float4* __restrict__ pages = t ? value_pages : key_pages;

    const float4* srcs[4];
#pragma unroll
    for (int j = 0; j < 4; j++) {
        unsigned idx = base + j * 256u;
        unsigned v   = idx;
        unsigned d4  = v & (D4 - 1);        v >>= 5;
        unsigned row = v & (PAGE_SIZE - 1);

        int b = (j < 2) ? b0 : b1;                      // page = p0 for j<2, p1 for j>=2
        unsigned h   = (idx >> 21) & (HPM - 1);
        unsigned s    = (unsigned)b * PAGE_SIZE + row;
        unsigned offA = (s * HPM + h) * D4 + d4;        // key/value (transpose folded)
        unsigned offB = idx & (INNER_F4 - 1);           // pass-through pages
        srcs[j] = (b >= 0) ? (kv + offA) : (pages + offB);
    }

    float4 vals[4];
#pragma unroll
    for (int j = 0; j < 4; j++) vals[j] = __ldg(srcs[j]);   // 4 back-to-back LDG.128

#pragma unroll
    for (int j = 0; j < 4; j++) out[base + j * 256u] = vals[j];
}

// ---------------------------------------------------------------------------
// Launch — single kernel, no inter-kernel dependency.
// Inputs: key, value, key_pages, value_pages, page_indices, seq_page_indices,
//         slot, true_length
// Output: concat(pages[2,H,P,PS,D], page_indices[4096], seq_page_indices[2048])
// ---------------------------------------------------------------------------
extern "C" void kernel_launch(void* const* d_in, const int* in_sizes, int n_in,
                              void* d_out, int out_size)
{
    const float* key          = (const float*)d_in[0];
    const float* value        = (const float*)d_in[1];
    const float* key_pages    = (const float*)d_in[2];
    const float* value_pages  = (const float*)d_in[3];
    const int*   page_indices = (const int*)d_in[4];
    const int*   seq_page_ind = (const int*)d_in[5];
    const int*   slot         = (const int*)d_in[6];
    const int*   true_length  = (const int*)d_in[7];

    float* out_pages = (float*)d_out;
    float* out_pi    = out_pages + PAGES_ELEMS;
    float* out_spi   = out_pi + NUM_PAGES;

    fused_pages_kernel<<<NBLOCKS, NTHREADS>>>(
        (const float4*)key, (const float4*)value,
        (const float4*)key_pages, (const float4*)value_pages,
        page_indices, seq_page_ind, slot, true_length,
        (float4*)out_pages, out_pi, out_spi);
}

// round 5
// speedup vs baseline: 1.1048x; 1.1048x over previous
#include <cuda_runtime.h>
#include <cuda_bf16.h>
#include <cstdint>

// Problem constants (fixed by setup_inputs)
#define HPM       8
#define NUM_PAGES 4096
#define PAGE_SIZE 16
#define DPM       128
#define MAX_SEQS  8
#define MAX_PPS   256
#define D4        (DPM / 4)                                    // 32 float4 per row
#define PAGES_ELEMS (2LL * HPM * NUM_PAGES * PAGE_SIZE * DPM)  // 134,217,728 floats
#define INNER_F4  (HPM * NUM_PAGES * PAGE_SIZE * D4)           // 1<<24 float4 per tensor
#define TOTAL_F4  (2u * INNER_F4)                              // 1<<25

// Scratch (device globals — no allocation allowed)
__device__ int g_blk_of_page[NUM_PAGES];   // -1 => keep old contents, else block index
__device__ int g_page_of_block[MAX_PPS];

// ---------------------------------------------------------------------------
// Kernel A (slim): first-fit allocation + small outputs. 256 threads,
// 16 pages each, int4 loads. Publishes g_blk_of_page then triggers PDL
// completion so the assemble kernel can start consuming it while this
// kernel finishes the small outputs.
// ---------------------------------------------------------------------------
__global__ void __launch_bounds__(256)
setup_kernel(const int* __restrict__ page_indices,
             const int* __restrict__ seq_page_indices,
             const int* __restrict__ slot_p,
             const int* __restrict__ true_length_p,
             float* __restrict__ out_pi,
             float* __restrict__ out_spi)
{
    __shared__ int s_base[8];
    const int tid  = threadIdx.x;
    const int lane = tid & 31;
    const int wrp  = tid >> 5;

    // Free flags: 16 pages per thread via int4 (page 0 reserved)
    int fl[16];
    int cnt = 0;
    {
        const int4* pi4 = (const int4*)page_indices;
#pragma unroll
        for (int k = 0; k < 4; k++) {
            int4 v = __ldg(&pi4[tid * 4 + k]);
            int bp = tid * 16 + k * 4;
            fl[k * 4 + 0] = (bp + 0 >= 1) && (v.x == 0);
            fl[k * 4 + 1] = (v.y == 0);
            fl[k * 4 + 2] = (v.z == 0);
            fl[k * 4 + 3] = (v.w == 0);
        }
#pragma unroll
        for (int j = 0; j < 16; j++) cnt += fl[j];
    }

    // Warp inclusive scan of per-thread counts
    int incl = cnt;
#pragma unroll
    for (int off = 1; off < 32; off <<= 1) {
        int n = __shfl_up_sync(0xffffffffu, incl, off);
        if (lane >= off) incl += n;
    }
    if (lane == 31) s_base[wrp] = incl;
    __syncthreads();

    // Warp 0 (first 8 lanes) scans the 8 warp totals (exclusive)
    if (wrp == 0 && lane < 8) {
        int v = s_base[lane];
        int s = v;
#pragma unroll
        for (int off = 1; off < 8; off <<= 1) {
            int n = __shfl_up_sync(0xffu, s, off);
            if (lane >= off) s += n;
        }
        s_base[lane] = s - v;
    }
    __syncthreads();

    const int excl = s_base[wrp] + (incl - cnt);

    const int tl = __ldg(true_length_p);
    int nb = (tl + PAGE_SIZE - 1) / PAGE_SIZE;
    if (nb > MAX_PPS) nb = MAX_PPS;

    // Assign block indices to first nb free pages; publish mapping tables
    int run = excl;
    float pi_out[16];
#pragma unroll
    for (int j = 0; j < 16; j++) {
        int p = tid * 16 + j;
        int b = -1;
        if (fl[j]) {
            if (run < nb) { b = run; g_page_of_block[run] = p; }
            run++;
        }
        g_blk_of_page[p] = b;
        pi_out[j] = (b >= 0) ? 1.0f : (float)__ldg(&page_indices[p]);
    }

    // Publish g_blk_of_page for the PDL-launched assemble kernel.
    __threadfence();
    __syncthreads();
    cudaTriggerProgrammaticLaunchCompletion();

    // Tail: small outputs (overlapped with assemble's launch/prologue)
#pragma unroll
    for (int k = 0; k < 4; k++) {
        float4 v = make_float4(pi_out[k*4+0], pi_out[k*4+1], pi_out[k*4+2], pi_out[k*4+3]);
        ((float4*)out_pi)[tid * 4 + k] = v;
    }

    const int slot = __ldg(slot_p);
    for (int i = tid; i < MAX_SEQS * MAX_PPS; i += 256) {
        int r = i >> 8, c = i & 255;
        float v = (float)__ldg(&seq_page_indices[i]);
        if (r == slot && c < nb) v = (float)g_page_of_block[c];
        out_spi[i] = v;
    }
}

// ---------------------------------------------------------------------------
// Kernel B: assemble [2, H, P, PS, D] — byte-identical structure to the R2
// winner (151 us, DRAM 85%), plus a grid-dependency sync placed after the
// pure-index prologue and before the g_blk_of_page read.
// ---------------------------------------------------------------------------
__global__ void __launch_bounds__(256)
assemble_pages_kernel(const float4* __restrict__ key,        // [1, S, H, D]
                      const float4* __restrict__ value,
                      const float4* __restrict__ key_pages,  // [H, P, PS, D]
                      const float4* __restrict__ value_pages,
                      float4* __restrict__ out)               // [2, H, P, PS, D]
{
    const unsigned base = blockIdx.x * 1024u + threadIdx.x;  // block covers 1024 f4
    const unsigned t = base >> 24;                            // 0 = key, 1 = value (uniform)
    const float4* __restrict__ kv    = t ? value       : key;
    const float4* __restrict__ pages = t ? value_pages : key_pages;

    // Pure-index prologue (independent of setup kernel)
    unsigned d4s[4], rows[4], ps[4], hs[4], offBs[4];
#pragma unroll
    for (int j = 0; j < 4; j++) {
        unsigned idx = base + j * 256u;
        unsigned v   = idx;
        d4s[j]  = v & (D4 - 1);        v >>= 5;
        rows[j] = v & (PAGE_SIZE - 1); v >>= 4;
        ps[j]   = v & (NUM_PAGES - 1); v >>= 12;
        hs[j]   = v & (HPM - 1);
        offBs[j] = idx & (INNER_F4 - 1);
    }

    // Wait for setup kernel's g_blk_of_page publication (PDL)
    cudaGridDependencySynchronize();

    const float4* srcs[4];
#pragma unroll
    for (int j = 0; j < 4; j++) {
        int b = g_blk_of_page[ps[j]];        // warp-uniform (16KB, L2-resident)
        unsigned s    = (unsigned)b * PAGE_SIZE + rows[j];
        unsigned offA = (s * HPM + hs[j]) * D4 + d4s[j];   // key/value (transpose folded)
        srcs[j] = (b >= 0) ? (kv + offA) : (pages + offBs[j]);
    }

    float4 vals[4];
#pragma unroll
    for (int j = 0; j < 4; j++) vals[j] = __ldg(srcs[j]);   // 4 back-to-back LDG.128

#pragma unroll
    for (int j = 0; j < 4; j++) out[base + j * 256u] = vals[j];
}

// ---------------------------------------------------------------------------
// Launch — setup, then assemble with programmatic dependent launch so its
// launch/prologue overlaps setup's tail.
// Inputs: key, value, key_pages, value_pages, page_indices, seq_page_indices,
//         slot, true_length
// Output: concat(pages[2,H,P,PS,D], page_indices[4096], seq_page_indices[2048])
// ---------------------------------------------------------------------------
extern "C" void kernel_launch(void* const* d_in, const int* in_sizes, int n_in,
                              void* d_out, int out_size)
{
    const float* key          = (const float*)d_in[0];
    const float* value        = (const float*)d_in[1];
    const float* key_pages    = (const float*)d_in[2];
    const float* value_pages  = (const float*)d_in[3];
    const int*   page_indices = (const int*)d_in[4];
    const int*   seq_page_ind = (const int*)d_in[5];
    const int*   slot         = (const int*)d_in[6];
    const int*   true_length  = (const int*)d_in[7];

    float* out_pages = (float*)d_out;
    float* out_pi    = out_pages + PAGES_ELEMS;
    float* out_spi   = out_pi + NUM_PAGES;

    setup_kernel<<<1, 256>>>(page_indices, seq_page_ind, slot, true_length,
                             out_pi, out_spi);

    // Assemble with PDL: may start while setup is still finishing its tail.
    cudaLaunchConfig_t cfg = {};
    cfg.gridDim  = dim3(TOTAL_F4 / 1024u, 1, 1);   // 32768
    cfg.blockDim = dim3(256, 1, 1);
    cfg.dynamicSmemBytes = 0;
    cfg.stream = 0;
    cudaLaunchAttribute attr[1];
    attr[0].id = cudaLaunchAttributeProgrammaticStreamSerialization;
    attr[0].val.programmaticStreamSerializationAllowed = 1;
    cfg.attrs = attr;
    cfg.numAttrs = 1;

    cudaLaunchKernelEx(&cfg, assemble_pages_kernel,
                       (const float4*)key, (const float4*)value,
                       (const float4*)key_pages, (const float4*)value_pages,
                       (float4*)out_pages);
}

// round 6
// speedup vs baseline: 1.1291x; 1.0219x over previous
#include <cuda_runtime.h>
#include <cuda_bf16.h>
#include <cstdint>

// Problem constants (fixed by setup_inputs)
#define HPM       8
#define NUM_PAGES 4096
#define PAGE_SIZE 16
#define DPM       128
#define MAX_SEQS  8
#define MAX_PPS   256
#define D4        (DPM / 4)                                    // 32 float4 per row
#define PAGES_ELEMS (2LL * HPM * NUM_PAGES * PAGE_SIZE * DPM)  // 134,217,728 floats
#define INNER_F4  (HPM * NUM_PAGES * PAGE_SIZE * D4)           // 1<<24 float4 per tensor
#define TOTAL_F4  (2u * INNER_F4)                              // 1<<25

// Scratch (device globals — no allocation allowed)
__device__ int g_blk_of_page[NUM_PAGES];   // -1 => keep old contents, else block index
__device__ int g_page_of_block[MAX_PPS];

// ---------------------------------------------------------------------------
// Kernel A (slim): first-fit allocation + small outputs. 256 threads,
// 16 pages each via int4 loads, warp-shuffle scan, vectorized stores.
// ---------------------------------------------------------------------------
__global__ void __launch_bounds__(256)
setup_kernel(const int* __restrict__ page_indices,
             const int* __restrict__ seq_page_indices,
             const int* __restrict__ slot_p,
             const int* __restrict__ true_length_p,
             float* __restrict__ out_pi,
             float* __restrict__ out_spi)
{
    __shared__ int s_base[8];
    const int tid  = threadIdx.x;
    const int lane = tid & 31;
    const int wrp  = tid >> 5;

    // Free flags: 16 pages per thread via int4 (page 0 reserved)
    int fl[16];
    int cnt = 0;
    {
        const int4* pi4 = (const int4*)page_indices;
#pragma unroll
        for (int k = 0; k < 4; k++) {
            int4 v = __ldg(&pi4[tid * 4 + k]);
            int bp = tid * 16 + k * 4;
            fl[k * 4 + 0] = (bp + 0 >= 1) && (v.x == 0);
            fl[k * 4 + 1] = (v.y == 0);
            fl[k * 4 + 2] = (v.z == 0);
            fl[k * 4 + 3] = (v.w == 0);
        }
#pragma unroll
        for (int j = 0; j < 16; j++) cnt += fl[j];
    }

    // Warp inclusive scan of per-thread counts
    int incl = cnt;
#pragma unroll
    for (int off = 1; off < 32; off <<= 1) {
        int n = __shfl_up_sync(0xffffffffu, incl, off);
        if (lane >= off) incl += n;
    }
    if (lane == 31) s_base[wrp] = incl;
    __syncthreads();

    // Warp 0 (first 8 lanes) scans the 8 warp totals (exclusive)
    if (wrp == 0 && lane < 8) {
        int v = s_base[lane];
        int s = v;
#pragma unroll
        for (int off = 1; off < 8; off <<= 1) {
            int n = __shfl_up_sync(0xffu, s, off);
            if (lane >= off) s += n;
        }
        s_base[lane] = s - v;
    }
    __syncthreads();

    const int excl = s_base[wrp] + (incl - cnt);

    const int tl = __ldg(true_length_p);
    int nb = (tl + PAGE_SIZE - 1) / PAGE_SIZE;
    if (nb > MAX_PPS) nb = MAX_PPS;

    // Assign block indices to first nb free pages; publish mapping tables
    int run = excl;
    float pi_out[16];
#pragma unroll
    for (int j = 0; j < 16; j++) {
        int p = tid * 16 + j;
        int b = -1;
        if (fl[j]) {
            if (run < nb) { b = run; g_page_of_block[run] = p; }
            run++;
        }
        g_blk_of_page[p] = b;
        pi_out[j] = (b >= 0) ? 1.0f : (float)__ldg(&page_indices[p]);
    }

    // page_indices output (vectorized)
#pragma unroll
    for (int k = 0; k < 4; k++) {
        float4 v = make_float4(pi_out[k*4+0], pi_out[k*4+1], pi_out[k*4+2], pi_out[k*4+3]);
        ((float4*)out_pi)[tid * 4 + k] = v;
    }

    __syncthreads();   // g_page_of_block visible block-wide

    // seq_page_indices output (8 x 256)
    const int slot = __ldg(slot_p);
#pragma unroll
    for (int k = 0; k < 8; k++) {
        int i = tid + k * 256;
        int r = i >> 8, c = i & 255;
        float v = (float)__ldg(&seq_page_indices[i]);
        if (r == slot && c < nb) v = (float)g_page_of_block[c];
        out_spi[i] = v;
    }
}

// ---------------------------------------------------------------------------
// Kernel B: assemble [2, H, P, PS, D] — the measured-best body (150.0 us,
// DRAM 85.7%, regs 24): 4 independent float4 per thread, block-uniform
// tensor select, predicated pointer select per element.
// ---------------------------------------------------------------------------
__global__ void __launch_bounds__(256)
assemble_pages_kernel(const float4* __restrict__ key,        // [1, S, H, D]
                      const float4* __restrict__ value,
                      const float4* __restrict__ key_pages,  // [H, P, PS, D]
                      const float4* __restrict__ value_pages,
                      float4* __restrict__ out)               // [2, H, P, PS, D]
{
    const unsigned base = blockIdx.x * 1024u + threadIdx.x;  // block covers 1024 f4
    const unsigned t = base >> 24;                            // 0 = key, 1 = value (uniform)
    const float4* __restrict__ kv    = t ? value       : key;
    const float4* __restrict__ pages = t ? value_pages : key_pages;

    const float4* srcs[4];
#pragma unroll
    for (int j = 0; j < 4; j++) {
        unsigned idx = base + j * 256u;
        unsigned v   = idx;
        unsigned d4  = v & (D4 - 1);        v >>= 5;
        unsigned row = v & (PAGE_SIZE - 1); v >>= 4;
        unsigned p   = v & (NUM_PAGES - 1); v >>= 12;
        unsigned h   = v & (HPM - 1);

        int b = g_blk_of_page[p];            // warp-uniform (16KB, L2-resident)
        unsigned s    = (unsigned)b * PAGE_SIZE + row;
        unsigned offA = (s * HPM + h) * D4 + d4;        // key/value (transpose folded)
        unsigned offB = idx & (INNER_F4 - 1);           // pass-through pages
        srcs[j] = (b >= 0) ? (kv + offA) : (pages + offB);
    }

    float4 vals[4];
#pragma unroll
    for (int j = 0; j < 4; j++) vals[j] = __ldg(srcs[j]);   // 4 back-to-back LDG.128

#pragma unroll
    for (int j = 0; j < 4; j++) out[base + j * 256u] = vals[j];
}

// ---------------------------------------------------------------------------
// Launch — two plain kernel nodes (no PDL, no flags).
// Inputs: key, value, key_pages, value_pages, page_indices, seq_page_indices,
//         slot, true_length
// Output: concat(pages[2,H,P,PS,D], page_indices[4096], seq_page_indices[2048])
// ---------------------------------------------------------------------------
extern "C" void kernel_launch(void* const* d_in, const int* in_sizes, int n_in,
                              void* d_out, int out_size)
{
    const float* key          = (const float*)d_in[0];
    const float* value        = (const float*)d_in[1];
    const float* key_pages    = (const float*)d_in[2];
    const float* value_pages  = (const float*)d_in[3];
    const int*   page_indices = (const int*)d_in[4];
    const int*   seq_page_ind = (const int*)d_in[5];
    const int*   slot         = (const int*)d_in[6];
    const int*   true_length  = (const int*)d_in[7];

    float* out_pages = (float*)d_out;
    float* out_pi    = out_pages + PAGES_ELEMS;
    float* out_spi   = out_pi + NUM_PAGES;

    setup_kernel<<<1, 256>>>(page_indices, seq_page_ind, slot, true_length,
                             out_pi, out_spi);

    assemble_pages_kernel<<<TOTAL_F4 / 1024u, 256>>>(
        (const float4*)key, (const float4*)value,
        (const float4*)key_pages, (const float4*)value_pages,
        (float4*)out_pages);
}

// round 7
// speedup vs baseline: 1.1317x; 1.0023x over previous
#include <cuda_runtime.h>
#include <cuda_bf16.h>
#include <cstdint>

// Problem constants (fixed by setup_inputs)
#define HPM       8
#define NUM_PAGES 4096
#define PAGE_SIZE 16
#define DPM       128
#define MAX_SEQS  8
#define MAX_PPS   256
#define D4        (DPM / 4)                                    // 32 float4 per row
#define PAGES_ELEMS (2LL * HPM * NUM_PAGES * PAGE_SIZE * DPM)  // 134,217,728 floats
#define INNER_F4  (HPM * NUM_PAGES * PAGE_SIZE * D4)           // 1<<24 float4 per tensor
#define TOTAL_F4  (2u * INNER_F4)                              // 1<<25

// Scratch (device globals — no allocation allowed)
__device__ int g_blk_of_page[NUM_PAGES];   // -1 => keep old contents, else block index
__device__ int g_page_of_block[MAX_PPS];

// ---------------------------------------------------------------------------
// Kernel A (minimal critical path): first-fit allocation scan + mapping
// tables + out_pi only. One 16KB read phase, one scan, one write phase.
// out_spi moved to assemble block 0 (depends only on the tables).
// ---------------------------------------------------------------------------
__global__ void __launch_bounds__(256)
setup_kernel(const int* __restrict__ page_indices,
             const int* __restrict__ true_length_p,
             float* __restrict__ out_pi)
{
    __shared__ int s_base[8];
    const int tid  = threadIdx.x;
    const int lane = tid & 31;
    const int wrp  = tid >> 5;

    // Load 16 pages per thread via int4; keep values for pi_out.
    int vals[16];
    int fl[16];
    int cnt = 0;
    {
        const int4* pi4 = (const int4*)page_indices;
#pragma unroll
        for (int k = 0; k < 4; k++) {
            int4 v = __ldg(&pi4[tid * 4 + k]);
            vals[k*4+0] = v.x; vals[k*4+1] = v.y;
            vals[k*4+2] = v.z; vals[k*4+3] = v.w;
        }
#pragma unroll
        for (int j = 0; j < 16; j++) {
            int p = tid * 16 + j;
            fl[j] = (p >= 1) && (vals[j] == 0);
            cnt += fl[j];
        }
    }

    // Warp inclusive scan of per-thread counts
    int incl = cnt;
#pragma unroll
    for (int off = 1; off < 32; off <<= 1) {
        int n = __shfl_up_sync(0xffffffffu, incl, off);
        if (lane >= off) incl += n;
    }
    if (lane == 31) s_base[wrp] = incl;
    __syncthreads();

    if (wrp == 0 && lane < 8) {
        int v = s_base[lane];
        int s = v;
#pragma unroll
        for (int off = 1; off < 8; off <<= 1) {
            int n = __shfl_up_sync(0xffu, s, off);
            if (lane >= off) s += n;
        }
        s_base[lane] = s - v;
    }
    __syncthreads();

    const int excl = s_base[wrp] + (incl - cnt);

    const int tl = __ldg(true_length_p);
    int nb = (tl + PAGE_SIZE - 1) / PAGE_SIZE;
    if (nb > MAX_PPS) nb = MAX_PPS;

    // Assign block indices to first nb free pages; publish tables + out_pi.
    int run = excl;
    float pi_out[16];
#pragma unroll
    for (int j = 0; j < 16; j++) {
        int p = tid * 16 + j;
        int b = -1;
        if (fl[j]) {
            if (run < nb) { b = run; g_page_of_block[run] = p; }
            run++;
        }
        g_blk_of_page[p] = b;
        pi_out[j] = (b >= 0) ? 1.0f : (float)vals[j];
    }

#pragma unroll
    for (int k = 0; k < 4; k++) {
        float4 v = make_float4(pi_out[k*4+0], pi_out[k*4+1], pi_out[k*4+2], pi_out[k*4+3]);
        ((float4*)out_pi)[tid * 4 + k] = v;
    }
}

// ---------------------------------------------------------------------------
// Kernel B: assemble [2, H, P, PS, D] — measured-best copy body unchanged.
// Block 0 additionally emits out_spi (depends on g_page_of_block, which the
// node edge already orders).
// ---------------------------------------------------------------------------
__global__ void __launch_bounds__(256)
assemble_pages_kernel(const float4* __restrict__ key,        // [1, S, H, D]
                      const float4* __restrict__ value,
                      const float4* __restrict__ key_pages,  // [H, P, PS, D]
                      const float4* __restrict__ value_pages,
                      const int*    __restrict__ seq_page_indices,
                      const int*    __restrict__ slot_p,
                      const int*    __restrict__ true_length_p,
                      float4* __restrict__ out,               // [2, H, P, PS, D]
                      float*  __restrict__ out_spi)           // [8, 256]
{
    // Block 0 tail-work: seq_page_indices output (tiny; no effect on the wave)
    if (blockIdx.x == 0) {
        const int tid = threadIdx.x;
        const int tl  = __ldg(true_length_p);
        int nb = (tl + PAGE_SIZE - 1) / PAGE_SIZE;
        if (nb > MAX_PPS) nb = MAX_PPS;
        const int slot = __ldg(slot_p);
#pragma unroll
        for (int k = 0; k < 8; k++) {
            int i = tid + k * 256;
            int r = i >> 8, c = i & 255;
            float v = (float)__ldg(&seq_page_indices[i]);
            if (r == slot && c < nb) v = (float)g_page_of_block[c];
            out_spi[i] = v;
        }
    }

    const unsigned base = blockIdx.x * 1024u + threadIdx.x;  // block covers 1024 f4
    const unsigned t = base >> 24;                            // 0 = key, 1 = value (uniform)
    const float4* __restrict__ kv    = t ? value       : key;
    const float4* __restrict__ pages = t ? value_pages : key_pages;

    const float4* srcs[4];
#pragma unroll
    for (int j = 0; j < 4; j++) {
        unsigned idx = base + j * 256u;
        unsigned v   = idx;
        unsigned d4  = v & (D4 - 1);        v >>= 5;
        unsigned row = v & (PAGE_SIZE - 1); v >>= 4;
        unsigned p   = v & (NUM_PAGES - 1); v >>= 12;
        unsigned h   = v & (HPM - 1);

        int b = g_blk_of_page[p];            // warp-uniform (16KB, L2-resident)
        unsigned s    = (unsigned)b * PAGE_SIZE + row;
        unsigned offA = (s * HPM + h) * D4 + d4;        // key/value (transpose folded)
        unsigned offB = idx & (INNER_F4 - 1);           // pass-through pages
        srcs[j] = (b >= 0) ? (kv + offA) : (pages + offB);
    }

    float4 vals[4];
#pragma unroll
    for (int j = 0; j < 4; j++) vals[j] = __ldg(srcs[j]);   // 4 back-to-back LDG.128

#pragma unroll
    for (int j = 0; j < 4; j++) out[base + j * 256u] = vals[j];
}

// ---------------------------------------------------------------------------
// Launch — two plain kernel nodes.
// Inputs: key, value, key_pages, value_pages, page_indices, seq_page_indices,
//         slot, true_length
// Output: concat(pages[2,H,P,PS,D], page_indices[4096], seq_page_indices[2048])
// ---------------------------------------------------------------------------
extern "C" void kernel_launch(void* const* d_in, const int* in_sizes, int n_in,
                              void* d_out, int out_size)
{
    const float* key          = (const float*)d_in[0];
    const float* value        = (const float*)d_in[1];
    const float* key_pages    = (const float*)d_in[2];
    const float* value_pages  = (const float*)d_in[3];
    const int*   page_indices = (const int*)d_in[4];
    const int*   seq_page_ind = (const int*)d_in[5];
    const int*   slot         = (const int*)d_in[6];
    const int*   true_length  = (const int*)d_in[7];

    float* out_pages = (float*)d_out;
    float* out_pi    = out_pages + PAGES_ELEMS;
    float* out_spi   = out_pi + NUM_PAGES;

    setup_kernel<<<1, 256>>>(page_indices, true_length, out_pi);

    assemble_pages_kernel<<<TOTAL_F4 / 1024u, 256>>>(
        (const float4*)key, (const float4*)value,
        (const float4*)key_pages, (const float4*)value_pages,
        seq_page_ind, slot, true_length,
        (float4*)out_pages, out_spi);
}

// round 8
// speedup vs baseline: 1.1501x; 1.0163x over previous
#include <cuda_runtime.h>
#include <cuda_bf16.h>
#include <cstdint>

// Problem constants (fixed by setup_inputs)
#define HPM       8
#define NUM_PAGES 4096
#define PAGE_SIZE 16
#define DPM       128
#define MAX_SEQS  8
#define MAX_PPS   256
#define D4        (DPM / 4)                                    // 32 float4 per row
#define PAGES_ELEMS (2LL * HPM * NUM_PAGES * PAGE_SIZE * DPM)  // 134,217,728 floats
#define INNER_F4  (HPM * NUM_PAGES * PAGE_SIZE * D4)           // 1<<24 float4 per tensor
#define TOTAL_F4  (2u * INNER_F4)                              // 1<<25

// Scratch (device globals — no allocation allowed)
__device__ int g_blk_of_page[NUM_PAGES];   // -1 => keep old contents, else block index
__device__ int g_page_of_block[MAX_PPS];

// ---------------------------------------------------------------------------
// Kernel A (slim): first-fit allocation + both small outputs. 256 threads.
// Both input reads issued up-front so their DRAM trips overlap.
// ---------------------------------------------------------------------------
__global__ void __launch_bounds__(256)
setup_kernel(const int* __restrict__ page_indices,
             const int* __restrict__ seq_page_indices,
             const int* __restrict__ slot_p,
             const int* __restrict__ true_length_p,
             float* __restrict__ out_pi,
             float* __restrict__ out_spi)
{
    __shared__ int s_base[8];
    const int tid  = threadIdx.x;
    const int lane = tid & 31;
    const int wrp  = tid >> 5;

    // Issue ALL global reads up front (page_indices 16KB, spi 8KB, scalars)
    const int4* pi4  = (const int4*)page_indices;
    const int4* spi4 = (const int4*)seq_page_indices;
    int4 pv[4], sv[2];
#pragma unroll
    for (int k = 0; k < 4; k++) pv[k] = __ldg(&pi4[tid * 4 + k]);
#pragma unroll
    for (int k = 0; k < 2; k++) sv[k] = __ldg(&spi4[tid * 2 + k]);
    const int tl   = __ldg(true_length_p);
    const int slot = __ldg(slot_p);

    int vals[16], fl[16];
    int cnt = 0;
#pragma unroll
    for (int k = 0; k < 4; k++) {
        vals[k*4+0] = pv[k].x; vals[k*4+1] = pv[k].y;
        vals[k*4+2] = pv[k].z; vals[k*4+3] = pv[k].w;
    }
#pragma unroll
    for (int j = 0; j < 16; j++) {
        int p = tid * 16 + j;
        fl[j] = (p >= 1) && (vals[j] == 0);
        cnt += fl[j];
    }

    // Warp inclusive scan of per-thread counts
    int incl = cnt;
#pragma unroll
    for (int off = 1; off < 32; off <<= 1) {
        int n = __shfl_up_sync(0xffffffffu, incl, off);
        if (lane >= off) incl += n;
    }
    if (lane == 31) s_base[wrp] = incl;
    __syncthreads();

    if (wrp == 0 && lane < 8) {
        int v = s_base[lane];
        int s = v;
#pragma unroll
        for (int off = 1; off < 8; off <<= 1) {
            int n = __shfl_up_sync(0xffu, s, off);
            if (lane >= off) s += n;
        }
        s_base[lane] = s - v;
    }
    __syncthreads();

    const int excl = s_base[wrp] + (incl - cnt);

    int nb = (tl + PAGE_SIZE - 1) / PAGE_SIZE;
    if (nb > MAX_PPS) nb = MAX_PPS;

    // Assign block indices; publish tables + out_pi.
    int run = excl;
    float pi_out[16];
#pragma unroll
    for (int j = 0; j < 16; j++) {
        int p = tid * 16 + j;
        int b = -1;
        if (fl[j]) {
            if (run < nb) { b = run; g_page_of_block[run] = p; }
            run++;
        }
        g_blk_of_page[p] = b;
        pi_out[j] = (b >= 0) ? 1.0f : (float)vals[j];
    }

#pragma unroll
    for (int k = 0; k < 4; k++) {
        float4 v = make_float4(pi_out[k*4+0], pi_out[k*4+1], pi_out[k*4+2], pi_out[k*4+3]);
        ((float4*)out_pi)[tid * 4 + k] = v;
    }

    __syncthreads();   // g_page_of_block visible block-wide

    // seq_page_indices output (values already in regs)
    int svals[8] = { sv[0].x, sv[0].y, sv[0].z, sv[0].w,
                     sv[1].x, sv[1].y, sv[1].z, sv[1].w };
#pragma unroll
    for (int j = 0; j < 8; j++) {
        int i = tid * 8 + j;
        int r = i >> 8, c = i & 255;
        float v = (float)svals[j];
        if (r == slot && c < nb) v = (float)g_page_of_block[c];
        out_spi[i] = v;
    }
}

// ---------------------------------------------------------------------------
// Kernel B: assemble [2, H, P, PS, D] — proven body with evict-first (.cs)
// loads and stores: every byte is touched exactly once, so keep both streams
// out of L2's retained set.
// ---------------------------------------------------------------------------
__global__ void __launch_bounds__(256)
assemble_pages_kernel(const float4* __restrict__ key,        // [1, S, H, D]
                      const float4* __restrict__ value,
                      const float4* __restrict__ key_pages,  // [H, P, PS, D]
                      const float4* __restrict__ value_pages,
                      float4* __restrict__ out)               // [2, H, P, PS, D]
{
    const unsigned base = blockIdx.x * 1024u + threadIdx.x;  // block covers 1024 f4
    const unsigned t = base >> 24;                            // 0 = key, 1 = value (uniform)
    const float4* __restrict__ kv    = t ? value       : key;
    const float4* __restrict__ pages = t ? value_pages : key_pages;

    const float4* srcs[4];
#pragma unroll
    for (int j = 0; j < 4; j++) {
        unsigned idx = base + j * 256u;
        unsigned v   = idx;
        unsigned d4  = v & (D4 - 1);        v >>= 5;
        unsigned row = v & (PAGE_SIZE - 1); v >>= 4;
        unsigned p   = v & (NUM_PAGES - 1); v >>= 12;
        unsigned h   = v & (HPM - 1);

        int b = g_blk_of_page[p];            // warp-uniform (16KB, L2-resident)
        unsigned s    = (unsigned)b * PAGE_SIZE + row;
        unsigned offA = (s * HPM + h) * D4 + d4;        // key/value (transpose folded)
        unsigned offB = idx & (INNER_F4 - 1);           // pass-through pages
        srcs[j] = (b >= 0) ? (kv + offA) : (pages + offB);
    }

    float4 vals[4];
#pragma unroll
    for (int j = 0; j < 4; j++) vals[j] = __ldcs(srcs[j]);   // 4 back-to-back LDG.128.CS

#pragma unroll
    for (int j = 0; j < 4; j++) __stcs(&out[base + j * 256u], vals[j]);
}

// ---------------------------------------------------------------------------
// Launch — two plain kernel nodes.
// Inputs: key, value, key_pages, value_pages, page_indices, seq_page_indices,
//         slot, true_length
// Output: concat(pages[2,H,P,PS,D], page_indices[4096], seq_page_indices[2048])
// ---------------------------------------------------------------------------
extern "C" void kernel_launch(void* const* d_in, const int* in_sizes, int n_in,
                              void* d_out, int out_size)
{
    const float* key          = (const float*)d_in[0];
    const float* value        = (const float*)d_in[1];
    const float* key_pages    = (const float*)d_in[2];
    const float* value_pages  = (const float*)d_in[3];
    const int*   page_indices = (const int*)d_in[4];
    const int*   seq_page_ind = (const int*)d_in[5];
    const int*   slot         = (const int*)d_in[6];
    const int*   true_length  = (const int*)d_in[7];

    float* out_pages = (float*)d_out;
    float* out_pi    = out_pages + PAGES_ELEMS;
    float* out_spi   = out_pi + NUM_PAGES;

    setup_kernel<<<1, 256>>>(page_indices, seq_page_ind, slot, true_length,
                             out_pi, out_spi);

    assemble_pages_kernel<<<TOTAL_F4 / 1024u, 256>>>(
        (const float4*)key, (const float4*)value,
        (const float4*)key_pages, (const float4*)value_pages,
        (float4*)out_pages);
}